// round 7
// baseline (speedup 1.0000x reference)
#include <cuda_runtime.h>
#include <cuda_fp16.h>
#include <cstdint>

// ============================================================================
// out[B, OUT] = x[B, IN] @ W[OUT, IN]^T + b[OUT], fp32, 4096^3.
// Plain sm_103 target -> fp16 HMMA single pass (products exact in fp32).
// R7: 512 threads / 16 warps (4 per SMSP, was 2) to close HMMA issue bubbles;
//     next-stage cp.async issued BEFORE the MMA block. Same proven tiling.
// ============================================================================

#define DIM 4096

__device__ __half g_xh[(size_t)DIM * DIM];
__device__ __half g_wh[(size_t)DIM * DIM];

// ----------------------------------------------------------------------------
// helpers
// ----------------------------------------------------------------------------
__device__ __forceinline__ uint32_t smem_u32(const void* p) {
    uint32_t a;
    asm("{ .reg .u64 t; cvta.to.shared.u64 t, %1; cvt.u32.u64 %0, t; }"
        : "=r"(a) : "l"(p));
    return a;
}

__device__ __forceinline__ void cp16(uint32_t dst, const void* src) {
    asm volatile("cp.async.cg.shared.global [%0], [%1], 16;"
                 :: "r"(dst), "l"(src));
}
#define CP_COMMIT() asm volatile("cp.async.commit_group;" ::: "memory")
#define CP_WAIT()   asm volatile("cp.async.wait_group 3;"  ::: "memory")

__device__ __forceinline__ void ldm4(uint32_t* r, uint32_t addr) {
    asm volatile("ldmatrix.sync.aligned.m8n8.x4.shared.b16 {%0,%1,%2,%3}, [%4];"
                 : "=r"(r[0]), "=r"(r[1]), "=r"(r[2]), "=r"(r[3]) : "r"(addr));
}

__device__ __forceinline__ void mma16816(float* d, const uint32_t* a, const uint32_t* b) {
    asm volatile(
        "mma.sync.aligned.m16n8k16.row.col.f32.f16.f16.f32 "
        "{%0,%1,%2,%3}, {%4,%5,%6,%7}, {%8,%9}, {%0,%1,%2,%3};"
        : "+f"(d[0]), "+f"(d[1]), "+f"(d[2]), "+f"(d[3])
        : "r"(a[0]), "r"(a[1]), "r"(a[2]), "r"(a[3]), "r"(b[0]), "r"(b[1]));
}

// ----------------------------------------------------------------------------
// Kernel 1: fp32 -> fp16 (both matrices in one launch)
// ----------------------------------------------------------------------------
__global__ void __launch_bounds__(256)
convert_half(const float* __restrict__ x, const float* __restrict__ W) {
    const int n4 = (DIM * DIM) / 4;
    for (int i = blockIdx.x * blockDim.x + threadIdx.x; i < 2 * n4;
         i += gridDim.x * blockDim.x) {
        const bool isw = i >= n4;
        const int j = isw ? i - n4 : i;
        float4 f = ((const float4*)(isw ? W : x))[j];
        __half2 h0 = __floats2half2_rn(f.x, f.y);
        __half2 h1 = __floats2half2_rn(f.z, f.w);
        uint2 pk;
        pk.x = *(const uint32_t*)&h0;
        pk.y = *(const uint32_t*)&h1;
        ((uint2*)(isw ? g_wh : g_xh))[j] = pk;
    }
}

// ----------------------------------------------------------------------------
// Kernel 2: fp16 HMMA GEMM. BM=256 BN=128 BK=32, 5 stages, 16 warps (8x2).
// ----------------------------------------------------------------------------
static constexpr int BM = 256;
static constexpr int BN = 128;
static constexpr int BK = 32;                    // fp16 elems (64B rows)
static constexpr int NK = DIM / BK;              // 128 iterations
static constexpr int NTHREADS = 512;

static constexpr int A_B = BM * BK * 2;          // 16384
static constexpr int B_B = BN * BK * 2;          // 8192
static constexpr int OFF_A = 0;
static constexpr int OFF_B = A_B;
static constexpr int STAGE_B = A_B + B_B;        // 24576
static constexpr int STAGES = 5;
static constexpr int SMEM_BYTES = STAGES * STAGE_B;  // 122880

// swizzled 16B-unit offset within a tile: row r (64B rows), unit u (0..3)
__device__ __forceinline__ uint32_t sw_off(int r, int u) {
    return (uint32_t)(r * 64 + ((u ^ ((r >> 1) & 3)) << 4));
}

// 1536 cp16 per stage / 512 threads = 3 each (2 for A, 1 for B)
__device__ __forceinline__ void load_stage(uint32_t st, int tm, int tn, int k0, int tid) {
#pragma unroll
    for (int i = 0; i < 2; i++) {
        int c = tid + i * NTHREADS;
        int r = c >> 2, u = c & 3;
        uint32_t sw = sw_off(r, u);
        size_t gx = (size_t)(tm * BM + r) * DIM + k0 + u * 8;
        cp16(st + OFF_A + sw, g_xh + gx);
    }
    {
        int c = tid;
        int r = c >> 2, u = c & 3;
        uint32_t sw = sw_off(r, u);
        size_t gw = (size_t)(tn * BN + r) * DIM + k0 + u * 8;
        cp16(st + OFF_B + sw, g_wh + gw);
    }
}

__global__ void __launch_bounds__(NTHREADS, 1)
gemm_kernel(const float* __restrict__ bias, float* __restrict__ out) {
    extern __shared__ char smem[];
    const uint32_t sb = smem_u32(smem);
    const int tid = threadIdx.x;
    const int wid = tid >> 5;
    const int lane = tid & 31;
    const int warp_m = wid & 7;      // 8 warps along M (32 rows each)
    const int warp_n = wid >> 3;     // 2 warps along N (64 cols each)

    // Grid: 16 tm x 32 tn = 512 CTAs.
    const int bid = blockIdx.x;
    const int tm = bid & 15;
    const int tn = bid >> 4;

    // ldmatrix lane addressing (proven mapping; warp tile 32x64)
    const int a_idx = lane >> 3;
    const int a_row = warp_m * 32 + (lane & 7) + (a_idx & 1) * 8;
    const int a_kk  = a_idx >> 1;
    const int a_sw  = (a_row >> 1) & 3;
    const int b_idx = lane >> 3;
    const int b_rr  = warp_n * 64 + (lane & 7) + (b_idx >> 1) * 8;
    const int b_kk  = b_idx & 1;
    const int b_sw  = (b_rr >> 1) & 3;

    uint32_t ua[2], ub[2];
#pragma unroll
    for (int ks = 0; ks < 2; ks++) {
        ua[ks] = (uint32_t)(((ks * 2 + a_kk) ^ a_sw) << 4);
        ub[ks] = (uint32_t)(((ks * 2 + b_kk) ^ b_sw) << 4);
    }
    const uint32_t a_base = (uint32_t)(a_row * 64);
    const uint32_t b_base = (uint32_t)(b_rr * 64);

    float acc[2][8][4];
#pragma unroll
    for (int mt = 0; mt < 2; mt++)
#pragma unroll
        for (int nt = 0; nt < 8; nt++)
#pragma unroll
            for (int j = 0; j < 4; j++) acc[mt][nt][j] = 0.f;

    // Prologue: fill STAGES-1 = 4 stages
#pragma unroll
    for (int s = 0; s < STAGES - 1; s++) {
        load_stage(sb + s * STAGE_B, tm, tn, s * BK, tid);
        CP_COMMIT();
    }

    int s_cur = 0;                  // stage of iteration kt
    int s_nxt = STAGES - 1;         // stage receiving kt + STAGES-1
    for (int kt = 0; kt < NK; kt++) {
        CP_WAIT();
        __syncthreads();

        // Issue next-stage loads FIRST: s_nxt's last readers finished at the
        // barrier above, and starting DRAM fetches early overlaps LDGSTS
        // traffic with the MMA-heavy phase below.
        const int kn = kt + STAGES - 1;
        if (kn < NK)
            load_stage(sb + s_nxt * STAGE_B, tm, tn, kn * BK, tid);
        CP_COMMIT();   // unconditional: keeps wait_group accounting exact

        const uint32_t stg = sb + s_cur * STAGE_B;
#pragma unroll
        for (int ks = 0; ks < 2; ks++) {
            uint32_t a[2][4];
            ldm4(a[0], stg + OFF_A + a_base + ua[ks]);
            ldm4(a[1], stg + OFF_A + a_base + 1024 + ua[ks]);
            uint32_t b[4][4];
#pragma unroll
            for (int p = 0; p < 4; p++)
                ldm4(b[p], stg + OFF_B + b_base + p * 1024 + ub[ks]);
#pragma unroll
            for (int mt = 0; mt < 2; mt++) {
#pragma unroll
                for (int nt = 0; nt < 8; nt++) {
                    const int p = nt >> 1, h = (nt & 1) * 2;
                    mma16816(acc[mt][nt], a[mt], &b[p][h]);
                }
            }
        }

        if (++s_cur == STAGES) s_cur = 0;
        if (++s_nxt == STAGES) s_nxt = 0;
    }

    // Epilogue: add bias, store fp32
    const int m0 = tm * BM + warp_m * 32;
    const int n0 = tn * BN + warp_n * 64;
    const int er = lane >> 2;
    const int ec = (lane & 3) * 2;
#pragma unroll
    for (int nt = 0; nt < 8; nt++) {
        const int col = n0 + nt * 8 + ec;
        const float b0 = __ldg(bias + col);
        const float b1 = __ldg(bias + col + 1);
#pragma unroll
        for (int mt = 0; mt < 2; mt++) {
            const int row = m0 + mt * 16 + er;
            float2 v0 = make_float2(acc[mt][nt][0] + b0, acc[mt][nt][1] + b1);
            float2 v1 = make_float2(acc[mt][nt][2] + b0, acc[mt][nt][3] + b1);
            *(float2*)(out + (size_t)row * DIM + col) = v0;
            *(float2*)(out + (size_t)(row + 8) * DIM + col) = v1;
        }
    }
}

// ----------------------------------------------------------------------------
// kernel_launch
// ----------------------------------------------------------------------------
extern "C" void kernel_launch(void* const* d_in, const int* in_sizes, int n_in,
                              void* d_out, int out_size) {
    const float* x = (const float*)d_in[0];
    const float* W = (const float*)d_in[1];
    const float* b = (const float*)d_in[2];
    float* out = (float*)d_out;

    cudaFuncSetAttribute(gemm_kernel,
                         cudaFuncAttributeMaxDynamicSharedMemorySize, SMEM_BYTES);

    convert_half<<<8192, 256>>>(x, W);

    const int grid = (DIM / BM) * (DIM / BN);   // 16 * 32 = 512
    gemm_kernel<<<grid, NTHREADS, SMEM_BYTES>>>(b, out);
}

// round 8
// speedup vs baseline: 1.0384x; 1.0384x over previous
#include <cuda_runtime.h>
#include <cuda_fp16.h>
#include <cstdint>

// ============================================================================
// out[B, OUT] = x[B, IN] @ W[OUT, IN]^T + b[OUT], fp32, 4096^3.
// Plain sm_103 target -> fp16 HMMA single pass (products exact in fp32).
// R8: BK 32->64 (one barrier per 2048 tensor-cyc instead of 1024), 128B-row
//     SW128 swizzle, 4 stages x 48KB = 192KB smem. Attacks the LDSM/HMMA
//     convoy seen as tensor=58% + L1=49% in R5-R7.
// ============================================================================

#define DIM 4096

__device__ __half g_xh[(size_t)DIM * DIM];
__device__ __half g_wh[(size_t)DIM * DIM];

// ----------------------------------------------------------------------------
// helpers
// ----------------------------------------------------------------------------
__device__ __forceinline__ uint32_t smem_u32(const void* p) {
    uint32_t a;
    asm("{ .reg .u64 t; cvta.to.shared.u64 t, %1; cvt.u32.u64 %0, t; }"
        : "=r"(a) : "l"(p));
    return a;
}

__device__ __forceinline__ void cp16(uint32_t dst, const void* src) {
    asm volatile("cp.async.cg.shared.global [%0], [%1], 16;"
                 :: "r"(dst), "l"(src));
}
#define CP_COMMIT() asm volatile("cp.async.commit_group;" ::: "memory")
#define CP_WAIT()   asm volatile("cp.async.wait_group 2;"  ::: "memory")

__device__ __forceinline__ void ldm4(uint32_t* r, uint32_t addr) {
    asm volatile("ldmatrix.sync.aligned.m8n8.x4.shared.b16 {%0,%1,%2,%3}, [%4];"
                 : "=r"(r[0]), "=r"(r[1]), "=r"(r[2]), "=r"(r[3]) : "r"(addr));
}

__device__ __forceinline__ void mma16816(float* d, const uint32_t* a, const uint32_t* b) {
    asm volatile(
        "mma.sync.aligned.m16n8k16.row.col.f32.f16.f16.f32 "
        "{%0,%1,%2,%3}, {%4,%5,%6,%7}, {%8,%9}, {%0,%1,%2,%3};"
        : "+f"(d[0]), "+f"(d[1]), "+f"(d[2]), "+f"(d[3])
        : "r"(a[0]), "r"(a[1]), "r"(a[2]), "r"(a[3]), "r"(b[0]), "r"(b[1]));
}

// ----------------------------------------------------------------------------
// Kernel 1: fp32 -> fp16 (both matrices in one launch)
// ----------------------------------------------------------------------------
__global__ void __launch_bounds__(256)
convert_half(const float* __restrict__ x, const float* __restrict__ W) {
    const int n4 = (DIM * DIM) / 4;
    for (int i = blockIdx.x * blockDim.x + threadIdx.x; i < 2 * n4;
         i += gridDim.x * blockDim.x) {
        const bool isw = i >= n4;
        const int j = isw ? i - n4 : i;
        float4 f = ((const float4*)(isw ? W : x))[j];
        __half2 h0 = __floats2half2_rn(f.x, f.y);
        __half2 h1 = __floats2half2_rn(f.z, f.w);
        uint2 pk;
        pk.x = *(const uint32_t*)&h0;
        pk.y = *(const uint32_t*)&h1;
        ((uint2*)(isw ? g_wh : g_xh))[j] = pk;
    }
}

// ----------------------------------------------------------------------------
// Kernel 2: fp16 HMMA GEMM. BM=256 BN=128 BK=64, 4 stages, 8 warps (4x2).
// Rows are 128B (64 fp16) -> full 8-way SW128 swizzle.
// ----------------------------------------------------------------------------
static constexpr int BM = 256;
static constexpr int BN = 128;
static constexpr int BK = 64;                    // fp16 elems (128B rows)
static constexpr int NK = DIM / BK;              // 64 iterations
static constexpr int NTHREADS = 256;

static constexpr int A_B = BM * BK * 2;          // 32768
static constexpr int B_B = BN * BK * 2;          // 16384
static constexpr int OFF_A = 0;
static constexpr int OFF_B = A_B;
static constexpr int STAGE_B = A_B + B_B;        // 49152
static constexpr int STAGES = 4;
static constexpr int SMEM_BYTES = STAGES * STAGE_B;  // 196608

// SW128 swizzle: row r (128B rows), 16B unit u in [0,8)
__device__ __forceinline__ uint32_t sw_off(int r, int u) {
    return (uint32_t)(r * 128 + ((u ^ (r & 7)) << 4));
}

// 3072 cp16 per stage / 256 threads = 12 each (8 for A, 4 for B)
__device__ __forceinline__ void load_stage(uint32_t st, int tm, int tn, int k0, int tid) {
#pragma unroll
    for (int i = 0; i < 8; i++) {
        int c = tid + i * NTHREADS;
        int r = c >> 3, u = c & 7;
        cp16(st + OFF_A + sw_off(r, u),
             g_xh + (size_t)(tm * BM + r) * DIM + k0 + u * 8);
    }
#pragma unroll
    for (int i = 0; i < 4; i++) {
        int c = tid + i * NTHREADS;
        int r = c >> 3, u = c & 7;
        cp16(st + OFF_B + sw_off(r, u),
             g_wh + (size_t)(tn * BN + r) * DIM + k0 + u * 8);
    }
}

__global__ void __launch_bounds__(NTHREADS, 1)
gemm_kernel(const float* __restrict__ bias, float* __restrict__ out) {
    extern __shared__ char smem[];
    const uint32_t sb = smem_u32(smem);
    const int tid = threadIdx.x;
    const int wid = tid >> 5;
    const int lane = tid & 31;
    const int warp_m = wid & 3;      // 4 warps along M (64 rows each)
    const int warp_n = wid >> 2;     // 2 warps along N (64 cols each)

    // Grid: 16 tm x 32 tn = 512 CTAs.
    const int bid = blockIdx.x;
    const int tm = bid & 15;
    const int tn = bid >> 4;

    // ldmatrix lane addressing, 128B rows.
    // A: 4 m-tiles of 16 rows; matrices (m0,k0),(m8,k0),(m0,k8),(m8,k8).
    const int a_idx = lane >> 3;
    const int a_row = warp_m * 64 + (lane & 7) + (a_idx & 1) * 8;
    const int a_kk  = a_idx >> 1;
    // B: 4 n-chunks of 16; matrices (n0,k0),(n0,k8),(n8,k0),(n8,k8).
    const int b_idx = lane >> 3;
    const int b_row = warp_n * 64 + (lane & 7) + (b_idx >> 1) * 8;
    const int b_kk  = b_idx & 1;
    const int lsw   = lane & 7;      // swizzle index (all row terms are mult of 8)

    uint32_t ua[4], ub[4];
#pragma unroll
    for (int ks = 0; ks < 4; ks++) {
        ua[ks] = (uint32_t)(((ks * 2 + a_kk) ^ lsw) << 4);
        ub[ks] = (uint32_t)(((ks * 2 + b_kk) ^ lsw) << 4);
    }
    const uint32_t a_base = (uint32_t)(a_row * 128);   // + mt*2048
    const uint32_t b_base = (uint32_t)(b_row * 128);   // + p*2048

    float acc[4][8][4];
#pragma unroll
    for (int mt = 0; mt < 4; mt++)
#pragma unroll
        for (int nt = 0; nt < 8; nt++)
#pragma unroll
            for (int j = 0; j < 4; j++) acc[mt][nt][j] = 0.f;

    // Prologue: fill STAGES-1 = 3 stages
#pragma unroll
    for (int s = 0; s < STAGES - 1; s++) {
        load_stage(sb + s * STAGE_B, tm, tn, s * BK, tid);
        CP_COMMIT();
    }

    for (int kt = 0; kt < NK; kt++) {
        CP_WAIT();
        __syncthreads();

        // Issue next-stage loads first (their stage was last read at kt-1).
        const int kn = kt + STAGES - 1;
        if (kn < NK)
            load_stage(sb + ((kt + STAGES - 1) & 3) * STAGE_B, tm, tn, kn * BK, tid);
        CP_COMMIT();   // unconditional: keeps wait_group accounting exact

        const uint32_t stg = sb + (kt & 3) * STAGE_B;
#pragma unroll
        for (int ks = 0; ks < 4; ks++) {
            uint32_t a[4][4];
#pragma unroll
            for (int mt = 0; mt < 4; mt++)
                ldm4(a[mt], stg + OFF_A + a_base + mt * 2048 + ua[ks]);
            uint32_t b[4][4];
#pragma unroll
            for (int p = 0; p < 4; p++)
                ldm4(b[p], stg + OFF_B + b_base + p * 2048 + ub[ks]);
#pragma unroll
            for (int mt = 0; mt < 4; mt++) {
#pragma unroll
                for (int nt = 0; nt < 8; nt++) {
                    const int p = nt >> 1, h = (nt & 1) * 2;
                    mma16816(acc[mt][nt], a[mt], &b[p][h]);
                }
            }
        }
    }

    // Epilogue: add bias, store fp32
    const int m0 = tm * BM + warp_m * 64;
    const int n0 = tn * BN + warp_n * 64;
    const int er = lane >> 2;
    const int ec = (lane & 3) * 2;
#pragma unroll
    for (int nt = 0; nt < 8; nt++) {
        const int col = n0 + nt * 8 + ec;
        const float b0 = __ldg(bias + col);
        const float b1 = __ldg(bias + col + 1);
#pragma unroll
        for (int mt = 0; mt < 4; mt++) {
            const int row = m0 + mt * 16 + er;
            float2 v0 = make_float2(acc[mt][nt][0] + b0, acc[mt][nt][1] + b1);
            float2 v1 = make_float2(acc[mt][nt][2] + b0, acc[mt][nt][3] + b1);
            *(float2*)(out + (size_t)row * DIM + col) = v0;
            *(float2*)(out + (size_t)(row + 8) * DIM + col) = v1;
        }
    }
}

// ----------------------------------------------------------------------------
// kernel_launch
// ----------------------------------------------------------------------------
extern "C" void kernel_launch(void* const* d_in, const int* in_sizes, int n_in,
                              void* d_out, int out_size) {
    const float* x = (const float*)d_in[0];
    const float* W = (const float*)d_in[1];
    const float* b = (const float*)d_in[2];
    float* out = (float*)d_out;

    cudaFuncSetAttribute(gemm_kernel,
                         cudaFuncAttributeMaxDynamicSharedMemorySize, SMEM_BYTES);

    convert_half<<<8192, 256>>>(x, W);

    const int grid = (DIM / BM) * (DIM / BN);   // 16 * 32 = 512
    gemm_kernel<<<grid, NTHREADS, SMEM_BYTES>>>(b, out);
}

// round 9
// speedup vs baseline: 1.2395x; 1.1936x over previous
#include <cuda_runtime.h>
#include <cuda_fp16.h>
#include <cstdint>

// ============================================================================
// out[B, OUT] = x[B, IN] @ W[OUT, IN]^T + b[OUT], fp32, 4096^3.
// Plain sm_103 target -> fp16 HMMA single pass (products exact in fp32).
// R9: 2 CTAs/SM (BM=128, 96KB smem, <=128 regs). Co-resident CTAs have
//     independent barriers -> one CTA's LDSM phase overlaps the other's
//     HMMA phase. Attacks the 60% tensor ceiling seen in R5-R8.
// ============================================================================

#define DIM 4096

__device__ __half g_xh[(size_t)DIM * DIM];
__device__ __half g_wh[(size_t)DIM * DIM];

// ----------------------------------------------------------------------------
// helpers
// ----------------------------------------------------------------------------
__device__ __forceinline__ uint32_t smem_u32(const void* p) {
    uint32_t a;
    asm("{ .reg .u64 t; cvta.to.shared.u64 t, %1; cvt.u32.u64 %0, t; }"
        : "=r"(a) : "l"(p));
    return a;
}

__device__ __forceinline__ void cp16(uint32_t dst, const void* src) {
    asm volatile("cp.async.cg.shared.global [%0], [%1], 16;"
                 :: "r"(dst), "l"(src));
}
#define CP_COMMIT() asm volatile("cp.async.commit_group;" ::: "memory")
#define CP_WAIT()   asm volatile("cp.async.wait_group 1;"  ::: "memory")

__device__ __forceinline__ void ldm4(uint32_t* r, uint32_t addr) {
    asm volatile("ldmatrix.sync.aligned.m8n8.x4.shared.b16 {%0,%1,%2,%3}, [%4];"
                 : "=r"(r[0]), "=r"(r[1]), "=r"(r[2]), "=r"(r[3]) : "r"(addr));
}

__device__ __forceinline__ void mma16816(float* d, const uint32_t* a, const uint32_t* b) {
    asm volatile(
        "mma.sync.aligned.m16n8k16.row.col.f32.f16.f16.f32 "
        "{%0,%1,%2,%3}, {%4,%5,%6,%7}, {%8,%9}, {%0,%1,%2,%3};"
        : "+f"(d[0]), "+f"(d[1]), "+f"(d[2]), "+f"(d[3])
        : "r"(a[0]), "r"(a[1]), "r"(a[2]), "r"(a[3]), "r"(b[0]), "r"(b[1]));
}

// ----------------------------------------------------------------------------
// Kernel 1: fp32 -> fp16 (both matrices in one launch)
// ----------------------------------------------------------------------------
__global__ void __launch_bounds__(256)
convert_half(const float* __restrict__ x, const float* __restrict__ W) {
    const int n4 = (DIM * DIM) / 4;
    for (int i = blockIdx.x * blockDim.x + threadIdx.x; i < 2 * n4;
         i += gridDim.x * blockDim.x) {
        const bool isw = i >= n4;
        const int j = isw ? i - n4 : i;
        float4 f = ((const float4*)(isw ? W : x))[j];
        __half2 h0 = __floats2half2_rn(f.x, f.y);
        __half2 h1 = __floats2half2_rn(f.z, f.w);
        uint2 pk;
        pk.x = *(const uint32_t*)&h0;
        pk.y = *(const uint32_t*)&h1;
        ((uint2*)(isw ? g_wh : g_xh))[j] = pk;
    }
}

// ----------------------------------------------------------------------------
// Kernel 2: fp16 HMMA GEMM. BM=128 BN=128 BK=64, 3 stages, 8 warps (4x2),
// 2 CTAs per SM. Rows are 128B -> full 8-way SW128 swizzle.
// ----------------------------------------------------------------------------
static constexpr int BM = 128;
static constexpr int BN = 128;
static constexpr int BK = 64;                    // fp16 elems (128B rows)
static constexpr int NK = DIM / BK;              // 64 iterations
static constexpr int NTHREADS = 256;

static constexpr int A_B = BM * BK * 2;          // 16384
static constexpr int B_B = BN * BK * 2;          // 16384
static constexpr int OFF_A = 0;
static constexpr int OFF_B = A_B;
static constexpr int STAGE_B = A_B + B_B;        // 32768
static constexpr int STAGES = 3;
static constexpr int SMEM_BYTES = STAGES * STAGE_B;  // 98304 -> 2 CTAs/SM

// SW128 swizzle: row r (128B rows), 16B unit u in [0,8)
__device__ __forceinline__ uint32_t sw_off(int r, int u) {
    return (uint32_t)(r * 128 + ((u ^ (r & 7)) << 4));
}

// 2048 cp16 per stage / 256 threads = 8 each (4 for A, 4 for B)
__device__ __forceinline__ void load_stage(uint32_t st, int tm, int tn, int k0, int tid) {
#pragma unroll
    for (int i = 0; i < 4; i++) {
        int c = tid + i * NTHREADS;
        int r = c >> 3, u = c & 7;
        cp16(st + OFF_A + sw_off(r, u),
             g_xh + (size_t)(tm * BM + r) * DIM + k0 + u * 8);
    }
#pragma unroll
    for (int i = 0; i < 4; i++) {
        int c = tid + i * NTHREADS;
        int r = c >> 3, u = c & 7;
        cp16(st + OFF_B + sw_off(r, u),
             g_wh + (size_t)(tn * BN + r) * DIM + k0 + u * 8);
    }
}

__global__ void __launch_bounds__(NTHREADS, 2)
gemm_kernel(const float* __restrict__ bias, float* __restrict__ out) {
    extern __shared__ char smem[];
    const uint32_t sb = smem_u32(smem);
    const int tid = threadIdx.x;
    const int wid = tid >> 5;
    const int lane = tid & 31;
    const int warp_m = wid & 3;      // 4 warps along M (32 rows each)
    const int warp_n = wid >> 2;     // 2 warps along N (64 cols each)

    // Grid: 32 tm x 32 tn = 1024 CTAs, tn-major.
    const int bid = blockIdx.x;
    const int tm = bid & 31;
    const int tn = bid >> 5;

    // ldmatrix lane addressing, 128B rows (proven R7/R8 fragment map).
    const int a_idx = lane >> 3;
    const int a_row = warp_m * 32 + (lane & 7) + (a_idx & 1) * 8;
    const int a_kk  = a_idx >> 1;
    const int b_idx = lane >> 3;
    const int b_row = warp_n * 64 + (lane & 7) + (b_idx >> 1) * 8;
    const int b_kk  = b_idx & 1;
    const int lsw   = lane & 7;

    uint32_t ua[4], ub[4];
#pragma unroll
    for (int ks = 0; ks < 4; ks++) {
        ua[ks] = (uint32_t)(((ks * 2 + a_kk) ^ lsw) << 4);
        ub[ks] = (uint32_t)(((ks * 2 + b_kk) ^ lsw) << 4);
    }
    const uint32_t a_base = (uint32_t)(a_row * 128);   // + mt*2048
    const uint32_t b_base = (uint32_t)(b_row * 128);   // + p*2048

    float acc[2][8][4];
#pragma unroll
    for (int mt = 0; mt < 2; mt++)
#pragma unroll
        for (int nt = 0; nt < 8; nt++)
#pragma unroll
            for (int j = 0; j < 4; j++) acc[mt][nt][j] = 0.f;

    // Prologue: fill STAGES-1 = 2 stages
#pragma unroll
    for (int s = 0; s < STAGES - 1; s++) {
        load_stage(sb + s * STAGE_B, tm, tn, s * BK, tid);
        CP_COMMIT();
    }

    int s_cur = 0;                  // stage of iteration kt
    int s_nxt = STAGES - 1;         // stage receiving kt + STAGES-1
    for (int kt = 0; kt < NK; kt++) {
        CP_WAIT();
        __syncthreads();

        // Issue next-stage loads first (that stage was last read at kt-1;
        // the barrier above makes the overwrite safe).
        const int kn = kt + STAGES - 1;
        if (kn < NK)
            load_stage(sb + s_nxt * STAGE_B, tm, tn, kn * BK, tid);
        CP_COMMIT();   // unconditional: keeps wait_group accounting exact

        const uint32_t stg = sb + s_cur * STAGE_B;
#pragma unroll
        for (int ks = 0; ks < 4; ks++) {
            uint32_t a[2][4];
            ldm4(a[0], stg + OFF_A + a_base + ua[ks]);
            ldm4(a[1], stg + OFF_A + a_base + 2048 + ua[ks]);
            uint32_t b[4][4];
#pragma unroll
            for (int p = 0; p < 4; p++)
                ldm4(b[p], stg + OFF_B + b_base + p * 2048 + ub[ks]);
#pragma unroll
            for (int mt = 0; mt < 2; mt++) {
#pragma unroll
                for (int nt = 0; nt < 8; nt++) {
                    const int p = nt >> 1, h = (nt & 1) * 2;
                    mma16816(acc[mt][nt], a[mt], &b[p][h]);
                }
            }
        }

        if (++s_cur == STAGES) s_cur = 0;
        if (++s_nxt == STAGES) s_nxt = 0;
    }

    // Epilogue: add bias, store fp32
    const int m0 = tm * BM + warp_m * 32;
    const int n0 = tn * BN + warp_n * 64;
    const int er = lane >> 2;
    const int ec = (lane & 3) * 2;
#pragma unroll
    for (int nt = 0; nt < 8; nt++) {
        const int col = n0 + nt * 8 + ec;
        const float b0 = __ldg(bias + col);
        const float b1 = __ldg(bias + col + 1);
#pragma unroll
        for (int mt = 0; mt < 2; mt++) {
            const int row = m0 + mt * 16 + er;
            float2 v0 = make_float2(acc[mt][nt][0] + b0, acc[mt][nt][1] + b1);
            float2 v1 = make_float2(acc[mt][nt][2] + b0, acc[mt][nt][3] + b1);
            *(float2*)(out + (size_t)row * DIM + col) = v0;
            *(float2*)(out + (size_t)(row + 8) * DIM + col) = v1;
        }
    }
}

// ----------------------------------------------------------------------------
// kernel_launch
// ----------------------------------------------------------------------------
extern "C" void kernel_launch(void* const* d_in, const int* in_sizes, int n_in,
                              void* d_out, int out_size) {
    const float* x = (const float*)d_in[0];
    const float* W = (const float*)d_in[1];
    const float* b = (const float*)d_in[2];
    float* out = (float*)d_out;

    cudaFuncSetAttribute(gemm_kernel,
                         cudaFuncAttributeMaxDynamicSharedMemorySize, SMEM_BYTES);

    convert_half<<<8192, 256>>>(x, W);

    const int grid = (DIM / BM) * (DIM / BN);   // 32 * 32 = 1024
    gemm_kernel<<<grid, NTHREADS, SMEM_BYTES>>>(b, out);
}

// round 10
// speedup vs baseline: 1.2533x; 1.0112x over previous
#include <cuda_runtime.h>
#include <cuda_fp16.h>
#include <cstdint>

// ============================================================================
// out[B, OUT] = x[B, IN] @ W[OUT, IN]^T + b[OUT], fp32, 4096^3.
// Plain sm_103 target -> fp16 HMMA single pass (products exact in fp32).
// R10: warp grid 4x2 -> 2x2 (warp tile 64x64). Smem re-reads drop 96->64KB
//      per CTA-iter; crossbar demand 2048 -> 1536 cyc vs 2048 tensor cyc.
//      Keeps R9's 2-CTA/SM phase decorrelation (the proven win).
// ============================================================================

#define DIM 4096

__device__ __half g_xh[(size_t)DIM * DIM];
__device__ __half g_wh[(size_t)DIM * DIM];

// ----------------------------------------------------------------------------
// helpers
// ----------------------------------------------------------------------------
__device__ __forceinline__ uint32_t smem_u32(const void* p) {
    uint32_t a;
    asm("{ .reg .u64 t; cvta.to.shared.u64 t, %1; cvt.u32.u64 %0, t; }"
        : "=r"(a) : "l"(p));
    return a;
}

__device__ __forceinline__ void cp16(uint32_t dst, const void* src) {
    asm volatile("cp.async.cg.shared.global [%0], [%1], 16;"
                 :: "r"(dst), "l"(src));
}
#define CP_COMMIT() asm volatile("cp.async.commit_group;" ::: "memory")
#define CP_WAIT()   asm volatile("cp.async.wait_group 1;"  ::: "memory")

__device__ __forceinline__ void ldm4(uint32_t* r, uint32_t addr) {
    asm volatile("ldmatrix.sync.aligned.m8n8.x4.shared.b16 {%0,%1,%2,%3}, [%4];"
                 : "=r"(r[0]), "=r"(r[1]), "=r"(r[2]), "=r"(r[3]) : "r"(addr));
}

__device__ __forceinline__ void mma16816(float* d, const uint32_t* a, const uint32_t* b) {
    asm volatile(
        "mma.sync.aligned.m16n8k16.row.col.f32.f16.f16.f32 "
        "{%0,%1,%2,%3}, {%4,%5,%6,%7}, {%8,%9}, {%0,%1,%2,%3};"
        : "+f"(d[0]), "+f"(d[1]), "+f"(d[2]), "+f"(d[3])
        : "r"(a[0]), "r"(a[1]), "r"(a[2]), "r"(a[3]), "r"(b[0]), "r"(b[1]));
}

// ----------------------------------------------------------------------------
// Kernel 1: fp32 -> fp16 (both matrices in one launch)
// ----------------------------------------------------------------------------
__global__ void __launch_bounds__(256)
convert_half(const float* __restrict__ x, const float* __restrict__ W) {
    const int n4 = (DIM * DIM) / 4;
    for (int i = blockIdx.x * blockDim.x + threadIdx.x; i < 2 * n4;
         i += gridDim.x * blockDim.x) {
        const bool isw = i >= n4;
        const int j = isw ? i - n4 : i;
        float4 f = ((const float4*)(isw ? W : x))[j];
        __half2 h0 = __floats2half2_rn(f.x, f.y);
        __half2 h1 = __floats2half2_rn(f.z, f.w);
        uint2 pk;
        pk.x = *(const uint32_t*)&h0;
        pk.y = *(const uint32_t*)&h1;
        ((uint2*)(isw ? g_wh : g_xh))[j] = pk;
    }
}

// ----------------------------------------------------------------------------
// Kernel 2: fp16 HMMA GEMM. BM=128 BN=128 BK=64, 3 stages, 4 warps (2x2),
// 2 CTAs per SM. Rows are 128B -> full 8-way SW128 swizzle.
// ----------------------------------------------------------------------------
static constexpr int BM = 128;
static constexpr int BN = 128;
static constexpr int BK = 64;                    // fp16 elems (128B rows)
static constexpr int NK = DIM / BK;              // 64 iterations
static constexpr int NTHREADS = 128;

static constexpr int A_B = BM * BK * 2;          // 16384
static constexpr int B_B = BN * BK * 2;          // 16384
static constexpr int OFF_A = 0;
static constexpr int OFF_B = A_B;
static constexpr int STAGE_B = A_B + B_B;        // 32768
static constexpr int STAGES = 3;
static constexpr int SMEM_BYTES = STAGES * STAGE_B;  // 98304 -> 2 CTAs/SM

// SW128 swizzle: row r (128B rows), 16B unit u in [0,8)
__device__ __forceinline__ uint32_t sw_off(int r, int u) {
    return (uint32_t)(r * 128 + ((u ^ (r & 7)) << 4));
}

// 2048 cp16 per stage / 128 threads = 16 each (8 for A, 8 for B)
__device__ __forceinline__ void load_stage(uint32_t st, int tm, int tn, int k0, int tid) {
#pragma unroll
    for (int i = 0; i < 8; i++) {
        int c = tid + i * NTHREADS;
        int r = c >> 3, u = c & 7;
        cp16(st + OFF_A + sw_off(r, u),
             g_xh + (size_t)(tm * BM + r) * DIM + k0 + u * 8);
    }
#pragma unroll
    for (int i = 0; i < 8; i++) {
        int c = tid + i * NTHREADS;
        int r = c >> 3, u = c & 7;
        cp16(st + OFF_B + sw_off(r, u),
             g_wh + (size_t)(tn * BN + r) * DIM + k0 + u * 8);
    }
}

__global__ void __launch_bounds__(NTHREADS, 2)
gemm_kernel(const float* __restrict__ bias, float* __restrict__ out) {
    extern __shared__ char smem[];
    const uint32_t sb = smem_u32(smem);
    const int tid = threadIdx.x;
    const int wid = tid >> 5;
    const int lane = tid & 31;
    const int warp_m = wid & 1;      // 2 warps along M (64 rows each)
    const int warp_n = wid >> 1;     // 2 warps along N (64 cols each)

    // Grid: 32 tm x 32 tn = 1024 CTAs, tn-major.
    const int bid = blockIdx.x;
    const int tm = bid & 31;
    const int tn = bid >> 5;

    // ldmatrix lane addressing, 128B rows (proven fragment map).
    // A: 4 m-tiles of 16 rows; matrices (m0,k0),(m8,k0),(m0,k8),(m8,k8).
    const int a_idx = lane >> 3;
    const int a_row = warp_m * 64 + (lane & 7) + (a_idx & 1) * 8;
    const int a_kk  = a_idx >> 1;
    // B: 4 n-chunks of 16; matrices (n0,k0),(n0,k8),(n8,k0),(n8,k8).
    const int b_idx = lane >> 3;
    const int b_row = warp_n * 64 + (lane & 7) + (b_idx >> 1) * 8;
    const int b_kk  = b_idx & 1;
    const int lsw   = lane & 7;

    uint32_t ua[4], ub[4];
#pragma unroll
    for (int ks = 0; ks < 4; ks++) {
        ua[ks] = (uint32_t)(((ks * 2 + a_kk) ^ lsw) << 4);
        ub[ks] = (uint32_t)(((ks * 2 + b_kk) ^ lsw) << 4);
    }
    const uint32_t a_base = (uint32_t)(a_row * 128);   // + mt*2048
    const uint32_t b_base = (uint32_t)(b_row * 128);   // + p*2048

    float acc[4][8][4];
#pragma unroll
    for (int mt = 0; mt < 4; mt++)
#pragma unroll
        for (int nt = 0; nt < 8; nt++)
#pragma unroll
            for (int j = 0; j < 4; j++) acc[mt][nt][j] = 0.f;

    // Prologue: fill STAGES-1 = 2 stages
#pragma unroll
    for (int s = 0; s < STAGES - 1; s++) {
        load_stage(sb + s * STAGE_B, tm, tn, s * BK, tid);
        CP_COMMIT();
    }

    int s_cur = 0;                  // stage of iteration kt
    int s_nxt = STAGES - 1;         // stage receiving kt + STAGES-1
    for (int kt = 0; kt < NK; kt++) {
        CP_WAIT();
        __syncthreads();

        // Issue next-stage loads first (that stage was last read at kt-1;
        // the barrier above makes the overwrite safe).
        const int kn = kt + STAGES - 1;
        if (kn < NK)
            load_stage(sb + s_nxt * STAGE_B, tm, tn, kn * BK, tid);
        CP_COMMIT();   // unconditional: keeps wait_group accounting exact

        const uint32_t stg = sb + s_cur * STAGE_B;
#pragma unroll
        for (int ks = 0; ks < 4; ks++) {
            uint32_t a[4][4];
#pragma unroll
            for (int mt = 0; mt < 4; mt++)
                ldm4(a[mt], stg + OFF_A + a_base + mt * 2048 + ua[ks]);
            uint32_t b[4][4];
#pragma unroll
            for (int p = 0; p < 4; p++)
                ldm4(b[p], stg + OFF_B + b_base + p * 2048 + ub[ks]);
#pragma unroll
            for (int mt = 0; mt < 4; mt++) {
#pragma unroll
                for (int nt = 0; nt < 8; nt++) {
                    const int p = nt >> 1, h = (nt & 1) * 2;
                    mma16816(acc[mt][nt], a[mt], &b[p][h]);
                }
            }
        }

        if (++s_cur == STAGES) s_cur = 0;
        if (++s_nxt == STAGES) s_nxt = 0;
    }

    // Epilogue: add bias, store fp32
    const int m0 = tm * BM + warp_m * 64;
    const int n0 = tn * BN + warp_n * 64;
    const int er = lane >> 2;
    const int ec = (lane & 3) * 2;
#pragma unroll
    for (int nt = 0; nt < 8; nt++) {
        const int col = n0 + nt * 8 + ec;
        const float b0 = __ldg(bias + col);
        const float b1 = __ldg(bias + col + 1);
#pragma unroll
        for (int mt = 0; mt < 4; mt++) {
            const int row = m0 + mt * 16 + er;
            float2 v0 = make_float2(acc[mt][nt][0] + b0, acc[mt][nt][1] + b1);
            float2 v1 = make_float2(acc[mt][nt][2] + b0, acc[mt][nt][3] + b1);
            *(float2*)(out + (size_t)row * DIM + col) = v0;
            *(float2*)(out + (size_t)(row + 8) * DIM + col) = v1;
        }
    }
}

// ----------------------------------------------------------------------------
// kernel_launch
// ----------------------------------------------------------------------------
extern "C" void kernel_launch(void* const* d_in, const int* in_sizes, int n_in,
                              void* d_out, int out_size) {
    const float* x = (const float*)d_in[0];
    const float* W = (const float*)d_in[1];
    const float* b = (const float*)d_in[2];
    float* out = (float*)d_out;

    cudaFuncSetAttribute(gemm_kernel,
                         cudaFuncAttributeMaxDynamicSharedMemorySize, SMEM_BYTES);

    convert_half<<<8192, 256>>>(x, W);

    const int grid = (DIM / BM) * (DIM / BN);   // 32 * 32 = 1024
    gemm_kernel<<<grid, NTHREADS, SMEM_BYTES>>>(b, out);
}

// round 11
// speedup vs baseline: 1.2576x; 1.0034x over previous
#include <cuda_runtime.h>
#include <cuda_fp16.h>
#include <cstdint>

// ============================================================================
// out[B, OUT] = x[B, IN] @ W[OUT, IN]^T + b[OUT], fp32, 4096^3.
// Plain sm_103 target -> fp16 HMMA single pass (products exact in fp32).
// R11: fragment double-buffering across ks (LDSM->MMA RAW bubble 4x -> 1x per
//      iteration); streaming stores in convert. Keeps R9/R10's 2-CTA/SM
//      decorrelation + 64KB/iter crossbar budget.
// ============================================================================

#define DIM 4096

__device__ __half g_xh[(size_t)DIM * DIM];
__device__ __half g_wh[(size_t)DIM * DIM];

// ----------------------------------------------------------------------------
// helpers
// ----------------------------------------------------------------------------
__device__ __forceinline__ uint32_t smem_u32(const void* p) {
    uint32_t a;
    asm("{ .reg .u64 t; cvta.to.shared.u64 t, %1; cvt.u32.u64 %0, t; }"
        : "=r"(a) : "l"(p));
    return a;
}

__device__ __forceinline__ void cp16(uint32_t dst, const void* src) {
    asm volatile("cp.async.cg.shared.global [%0], [%1], 16;"
                 :: "r"(dst), "l"(src));
}
#define CP_COMMIT() asm volatile("cp.async.commit_group;" ::: "memory")
#define CP_WAIT()   asm volatile("cp.async.wait_group 1;"  ::: "memory")

__device__ __forceinline__ void ldm4(uint32_t* r, uint32_t addr) {
    asm volatile("ldmatrix.sync.aligned.m8n8.x4.shared.b16 {%0,%1,%2,%3}, [%4];"
                 : "=r"(r[0]), "=r"(r[1]), "=r"(r[2]), "=r"(r[3]) : "r"(addr));
}

__device__ __forceinline__ void mma16816(float* d, const uint32_t* a, const uint32_t* b) {
    asm volatile(
        "mma.sync.aligned.m16n8k16.row.col.f32.f16.f16.f32 "
        "{%0,%1,%2,%3}, {%4,%5,%6,%7}, {%8,%9}, {%0,%1,%2,%3};"
        : "+f"(d[0]), "+f"(d[1]), "+f"(d[2]), "+f"(d[3])
        : "r"(a[0]), "r"(a[1]), "r"(a[2]), "r"(a[3]), "r"(b[0]), "r"(b[1]));
}

// ----------------------------------------------------------------------------
// Kernel 1: fp32 -> fp16 (both matrices in one launch), streaming stores
// ----------------------------------------------------------------------------
__global__ void __launch_bounds__(256)
convert_half(const float* __restrict__ x, const float* __restrict__ W) {
    const int n4 = (DIM * DIM) / 4;
    for (int i = blockIdx.x * blockDim.x + threadIdx.x; i < 2 * n4;
         i += gridDim.x * blockDim.x) {
        const bool isw = i >= n4;
        const int j = isw ? i - n4 : i;
        float4 f = ((const float4*)(isw ? W : x))[j];
        __half2 h0 = __floats2half2_rn(f.x, f.y);
        __half2 h1 = __floats2half2_rn(f.z, f.w);
        uint2 pk;
        pk.x = *(const uint32_t*)&h0;
        pk.y = *(const uint32_t*)&h1;
        __stcs((uint2*)(isw ? g_wh : g_xh) + j, pk);   // streaming: skip L2 fill
    }
}

// ----------------------------------------------------------------------------
// Kernel 2: fp16 HMMA GEMM. BM=128 BN=128 BK=64, 3 stages, 4 warps (2x2),
// 2 CTAs per SM, fragment double-buffering. 128B rows, 8-way SW128 swizzle.
// ----------------------------------------------------------------------------
static constexpr int BM = 128;
static constexpr int BN = 128;
static constexpr int BK = 64;                    // fp16 elems (128B rows)
static constexpr int NK = DIM / BK;              // 64 iterations
static constexpr int NTHREADS = 128;

static constexpr int A_B = BM * BK * 2;          // 16384
static constexpr int B_B = BN * BK * 2;          // 16384
static constexpr int OFF_A = 0;
static constexpr int OFF_B = A_B;
static constexpr int STAGE_B = A_B + B_B;        // 32768
static constexpr int STAGES = 3;
static constexpr int SMEM_BYTES = STAGES * STAGE_B;  // 98304 -> 2 CTAs/SM

// SW128 swizzle: row r (128B rows), 16B unit u in [0,8)
__device__ __forceinline__ uint32_t sw_off(int r, int u) {
    return (uint32_t)(r * 128 + ((u ^ (r & 7)) << 4));
}

// 2048 cp16 per stage / 128 threads = 16 each (8 for A, 8 for B)
__device__ __forceinline__ void load_stage(uint32_t st, int tm, int tn, int k0, int tid) {
#pragma unroll
    for (int i = 0; i < 8; i++) {
        int c = tid + i * NTHREADS;
        int r = c >> 3, u = c & 7;
        cp16(st + OFF_A + sw_off(r, u),
             g_xh + (size_t)(tm * BM + r) * DIM + k0 + u * 8);
    }
#pragma unroll
    for (int i = 0; i < 8; i++) {
        int c = tid + i * NTHREADS;
        int r = c >> 3, u = c & 7;
        cp16(st + OFF_B + sw_off(r, u),
             g_wh + (size_t)(tn * BN + r) * DIM + k0 + u * 8);
    }
}

__global__ void __launch_bounds__(NTHREADS, 2)
gemm_kernel(const float* __restrict__ bias, float* __restrict__ out) {
    extern __shared__ char smem[];
    const uint32_t sb = smem_u32(smem);
    const int tid = threadIdx.x;
    const int wid = tid >> 5;
    const int lane = tid & 31;
    const int warp_m = wid & 1;      // 2 warps along M (64 rows each)
    const int warp_n = wid >> 1;     // 2 warps along N (64 cols each)

    // Grid: 32 tm x 32 tn = 1024 CTAs, tn-major.
    const int bid = blockIdx.x;
    const int tm = bid & 31;
    const int tn = bid >> 5;

    // ldmatrix lane addressing, 128B rows (proven fragment map).
    const int a_idx = lane >> 3;
    const int a_row = warp_m * 64 + (lane & 7) + (a_idx & 1) * 8;
    const int a_kk  = a_idx >> 1;
    const int b_idx = lane >> 3;
    const int b_row = warp_n * 64 + (lane & 7) + (b_idx >> 1) * 8;
    const int b_kk  = b_idx & 1;
    const int lsw   = lane & 7;

    uint32_t ua[4], ub[4];
#pragma unroll
    for (int ks = 0; ks < 4; ks++) {
        ua[ks] = (uint32_t)(((ks * 2 + a_kk) ^ lsw) << 4);
        ub[ks] = (uint32_t)(((ks * 2 + b_kk) ^ lsw) << 4);
    }
    const uint32_t a_base = (uint32_t)(a_row * 128);   // + mt*2048
    const uint32_t b_base = (uint32_t)(b_row * 128);   // + p*2048

    float acc[4][8][4];
#pragma unroll
    for (int mt = 0; mt < 4; mt++)
#pragma unroll
        for (int nt = 0; nt < 8; nt++)
#pragma unroll
            for (int j = 0; j < 4; j++) acc[mt][nt][j] = 0.f;

    // Prologue: fill STAGES-1 = 2 stages
#pragma unroll
    for (int s = 0; s < STAGES - 1; s++) {
        load_stage(sb + s * STAGE_B, tm, tn, s * BK, tid);
        CP_COMMIT();
    }

    int s_cur = 0;                  // stage of iteration kt
    int s_nxt = STAGES - 1;         // stage receiving kt + STAGES-1
    for (int kt = 0; kt < NK; kt++) {
        CP_WAIT();
        __syncthreads();

        // Issue next-stage loads first (that stage was last read at kt-1;
        // the barrier above makes the overwrite safe).
        const int kn = kt + STAGES - 1;
        if (kn < NK)
            load_stage(sb + s_nxt * STAGE_B, tm, tn, kn * BK, tid);
        CP_COMMIT();   // unconditional: keeps wait_group accounting exact

        const uint32_t stg = sb + s_cur * STAGE_B;

        // Fragment double-buffer: preload ks=0, then prefetch ks+1 during MMA(ks)
        uint32_t a[2][4][4], b[2][4][4];
#pragma unroll
        for (int mt = 0; mt < 4; mt++)
            ldm4(a[0][mt], stg + OFF_A + a_base + mt * 2048 + ua[0]);
#pragma unroll
        for (int p = 0; p < 4; p++)
            ldm4(b[0][p], stg + OFF_B + b_base + p * 2048 + ub[0]);

#pragma unroll
        for (int ks = 0; ks < 4; ks++) {
            const int cur = ks & 1, nxt = cur ^ 1;
            if (ks < 3) {
#pragma unroll
                for (int mt = 0; mt < 4; mt++)
                    ldm4(a[nxt][mt], stg + OFF_A + a_base + mt * 2048 + ua[ks + 1]);
#pragma unroll
                for (int p = 0; p < 4; p++)
                    ldm4(b[nxt][p], stg + OFF_B + b_base + p * 2048 + ub[ks + 1]);
            }
#pragma unroll
            for (int mt = 0; mt < 4; mt++) {
#pragma unroll
                for (int nt = 0; nt < 8; nt++) {
                    const int p = nt >> 1, h = (nt & 1) * 2;
                    mma16816(acc[mt][nt], a[cur][mt], &b[cur][p][h]);
                }
            }
        }

        if (++s_cur == STAGES) s_cur = 0;
        if (++s_nxt == STAGES) s_nxt = 0;
    }

    // Epilogue: add bias, store fp32
    const int m0 = tm * BM + warp_m * 64;
    const int n0 = tn * BN + warp_n * 64;
    const int er = lane >> 2;
    const int ec = (lane & 3) * 2;
#pragma unroll
    for (int nt = 0; nt < 8; nt++) {
        const int col = n0 + nt * 8 + ec;
        const float b0 = __ldg(bias + col);
        const float b1 = __ldg(bias + col + 1);
#pragma unroll
        for (int mt = 0; mt < 4; mt++) {
            const int row = m0 + mt * 16 + er;
            float2 v0 = make_float2(acc[mt][nt][0] + b0, acc[mt][nt][1] + b1);
            float2 v1 = make_float2(acc[mt][nt][2] + b0, acc[mt][nt][3] + b1);
            *(float2*)(out + (size_t)row * DIM + col) = v0;
            *(float2*)(out + (size_t)(row + 8) * DIM + col) = v1;
        }
    }
}

// ----------------------------------------------------------------------------
// kernel_launch
// ----------------------------------------------------------------------------
extern "C" void kernel_launch(void* const* d_in, const int* in_sizes, int n_in,
                              void* d_out, int out_size) {
    const float* x = (const float*)d_in[0];
    const float* W = (const float*)d_in[1];
    const float* b = (const float*)d_in[2];
    float* out = (float*)d_out;

    cudaFuncSetAttribute(gemm_kernel,
                         cudaFuncAttributeMaxDynamicSharedMemorySize, SMEM_BYTES);

    convert_half<<<8192, 256>>>(x, W);

    const int grid = (DIM / BM) * (DIM / BN);   // 32 * 32 = 1024
    gemm_kernel<<<grid, NTHREADS, SMEM_BYTES>>>(b, out);
}